// round 10
// baseline (speedup 1.0000x reference)
#include <cuda_runtime.h>
#include <cstdint>
#include <cstddef>

#define OUT_F 8192
#define IN_F  8192
#define NCOL  16
#define KS     16                 // K-splits across blockIdx.y
#define KSLICE (IN_F / KS)        // 512 k per block
#define K4SL   (KSLICE / 4)       // 128 packed k4 per block
#define PAD    20                 // smem row stride in words (bank-conflict-free)
#define TPB    256
#define ROWS_PER_LANE 4
#define ROWS_PER_WARP 16          // 4 r-groups * 4 rows
#define ROWS_PER_BLK  128         // 8 warps * 16 rows
#define NGRP   (OUT_F / ROWS_PER_BLK)   // 64 row-groups
#define NITER  (K4SL / 8)         // 16: one k4 per kl-lane per iter

#define S1     0.0625f            // 2^-4
#define S1_INV 16.0f
#define S2     4.8828125e-4f      // 2^-11
#define S2_INV 2048.0f

// --- device scratch (no allocations allowed) ---
__device__ float4 psum4[KS * OUT_F * NCOL / 4];   // K-split partials (8 MiB)
__device__ int    g_cnt[NGRP];                    // arrival counters (self-resetting)

// Pack low bytes of 4 sign-extended int32 weights into one dp4a word.
__device__ __forceinline__ uint32_t packw(uint4 v) {
    return (v.x & 0xFFu) | ((v.y & 0xFFu) << 8) | ((v.z & 0xFFu) << 16) | (v.w << 24);
}

// ------------------------------------------------------------------
// Single fused kernel: quantize x slice into padded SMEM, dp4a GEMM
// with coalesced prefetched W loads, warp-shuffle k-reduction, K-split
// partials, and a last-arriving-block tail reduction into out.
//   lane = r*8 + kl:  r in 0..3 -> rows 4r..4r+3,  kl in 0..7 -> k4.
//   W LDG: 8 kl-lanes read 128B contiguous per row; prefetch depth 1
//   keeps 4 LDG.128 per lane in flight (~16KB/SM outstanding at occ 1).
//   x LDS: stride PAD=20 words -> banks 20*kl mod 32 all distinct.
// ------------------------------------------------------------------
__global__ __launch_bounds__(TPB, 1)
void gemm_kernel(const int* __restrict__ W, const float* __restrict__ x,
                 const float* __restrict__ scal, float4* __restrict__ out4) {
    __shared__ uint32_t s_a[K4SL * PAD];   // coarse int8 x, packed 4k/word
    __shared__ uint32_t s_b[K4SL * PAD];   // fine   int8 residual
    __shared__ int s_last;

    const int tid   = threadIdx.x;
    const int ky    = blockIdx.y;
    const int bx    = blockIdx.x;
    const int kbase = ky * KSLICE;

    // ---- stage + quantize x slice: x[k][c] row-major, k in [kbase, kbase+KSLICE) ----
    for (int slot = tid; slot < K4SL * NCOL; slot += TPB) {
        const int k4 = slot >> 4;
        const int c  = slot & 15;
        uint32_t pa = 0, pb = 0;
#pragma unroll
        for (int i = 0; i < 4; i++) {
            float v = x[(kbase + 4 * k4 + i) * NCOL + c];
            int ai = __float2int_rn(v * S1_INV);
            ai = max(-127, min(127, ai));
            float rres = v - (float)ai * S1;
            int bi = __float2int_rn(rres * S2_INV);
            bi = max(-127, min(127, bi));
            pa |= (uint32_t)(uint8_t)(signed char)ai << (8 * i);
            pb |= (uint32_t)(uint8_t)(signed char)bi << (8 * i);
        }
        s_a[k4 * PAD + c] = pa;
        s_b[k4 * PAD + c] = pb;
    }
    __syncthreads();

    // ---- main loop ----
    const int lane = tid & 31;
    const int wid  = tid >> 5;
    const int r    = lane >> 3;            // 0..3
    const int kl   = lane & 7;             // 0..7
    const int row0 = bx * ROWS_PER_BLK + wid * ROWS_PER_WARP + 4 * r;

    const int* wp = W + (size_t)row0 * IN_F + kbase;

    int acc_a[ROWS_PER_LANE][NCOL], acc_b[ROWS_PER_LANE][NCOL];
#pragma unroll
    for (int j = 0; j < ROWS_PER_LANE; j++)
#pragma unroll
        for (int c = 0; c < NCOL; c++) { acc_a[j][c] = 0; acc_b[j][c] = 0; }

    // prefetch iter 0
    uint4 pf[ROWS_PER_LANE];
#pragma unroll
    for (int j = 0; j < ROWS_PER_LANE; j++)
        pf[j] = __ldcs((const uint4*)(wp + (size_t)j * IN_F + kl * 4));

    for (int it = 0; it < NITER; it++) {
        const int k4 = it * 8 + kl;            // this lane's packed-k index

        uint32_t w[ROWS_PER_LANE];
#pragma unroll
        for (int j = 0; j < ROWS_PER_LANE; j++)
            w[j] = packw(pf[j]);

        if (it + 1 < NITER) {
            const int koff = ((it + 1) * 8 + kl) * 4;
#pragma unroll
            for (int j = 0; j < ROWS_PER_LANE; j++)
                pf[j] = __ldcs((const uint4*)(wp + (size_t)j * IN_F + koff));
        }

#pragma unroll
        for (int h = 0; h < 4; h++) {          // 4 columns at a time
            uint4 A = *(const uint4*)&s_a[k4 * PAD + 4 * h];
            uint4 B = *(const uint4*)&s_b[k4 * PAD + 4 * h];
            const uint32_t xa[4] = {A.x, A.y, A.z, A.w};
            const uint32_t xb[4] = {B.x, B.y, B.z, B.w};
#pragma unroll
            for (int c = 0; c < 4; c++) {
#pragma unroll
                for (int j = 0; j < ROWS_PER_LANE; j++) {
                    acc_a[j][4 * h + c] = __dp4a((int)w[j], (int)xa[c], acc_a[j][4 * h + c]);
                    acc_b[j][4 * h + c] = __dp4a((int)w[j], (int)xb[c], acc_b[j][4 * h + c]);
                }
            }
        }
    }

    // ---- combine levels (exact int -> float), reduce across the 8 kl-lanes ----
    const float s = scal[0];
    float res[ROWS_PER_LANE][NCOL];
#pragma unroll
    for (int j = 0; j < ROWS_PER_LANE; j++)
#pragma unroll
        for (int c = 0; c < NCOL; c++)
            res[j][c] = s * (S1 * (float)acc_a[j][c] + S2 * (float)acc_b[j][c]);

#pragma unroll
    for (int mask = 4; mask >= 1; mask >>= 1) {
#pragma unroll
        for (int j = 0; j < ROWS_PER_LANE; j++)
#pragma unroll
            for (int c = 0; c < NCOL; c++)
                res[j][c] += __shfl_xor_sync(0xFFFFFFFFu, res[j][c], mask);
    }

    if (kl == 0) {
#pragma unroll
        for (int j = 0; j < ROWS_PER_LANE; j++) {
            const int row = row0 + j;
            float4* dst = &psum4[((size_t)ky * OUT_F + row) * (NCOL / 4)];
#pragma unroll
            for (int c4 = 0; c4 < NCOL / 4; c4++)
                dst[c4] = make_float4(res[j][4 * c4], res[j][4 * c4 + 1],
                                      res[j][4 * c4 + 2], res[j][4 * c4 + 3]);
        }
    }

    // ---- tail: last of the KS blocks in this row-group reduces to out ----
    __threadfence();                 // publish psum writes
    if (tid == 0) {
        int old = atomicAdd(&g_cnt[bx], 1);
        int last = (old == KS - 1);
        if (last) g_cnt[bx] = 0;     // self-reset for next graph replay
        s_last = last;
    }
    __syncthreads();
    if (!s_last) return;
    __threadfence();                 // acquire other blocks' psum writes

    // this block reduces its 128 rows x 16 cols = 512 float4
    const int nf4 = ROWS_PER_BLK * NCOL / 4;            // 512
    for (int i4 = tid; i4 < nf4; i4 += TPB) {
        const int base = bx * nf4 + i4;                  // float4 index in slice 0
        float4 a = psum4[base];
#pragma unroll
        for (int j = 1; j < KS; j++) {
            float4 b = psum4[(size_t)j * (OUT_F * NCOL / 4) + base];
            a.x += b.x; a.y += b.y; a.z += b.z; a.w += b.w;
        }
        out4[base] = a;
    }
}

extern "C" void kernel_launch(void* const* d_in, const int* in_sizes, int n_in,
                              void* d_out, int out_size) {
    // Bind inputs by size (element counts; byte counts also accepted)
    const float* x    = nullptr;
    const int*   W    = nullptr;   // int8 weights delivered as int32 by harness
    const float* scal = nullptr;
    for (int i = 0; i < n_in; i++) {
        long sz = in_sizes[i];
        if (sz == (long)IN_F * NCOL || sz == (long)IN_F * NCOL * 4)
            x = (const float*)d_in[i];
        else if (sz == (long)OUT_F * IN_F || sz == (long)OUT_F * IN_F * 4)
            W = (const int*)d_in[i];
        else if (sz == 1 || sz == 4)
            scal = (const float*)d_in[i];
    }
    if (!x)    x    = (const float*)d_in[0];
    if (!W)    W    = (const int*)d_in[1];
    if (!scal) scal = (const float*)d_in[2];
    float4* out4 = (float4*)d_out;

    dim3 grid(NGRP, KS);   // (64, 16)
    gemm_kernel<<<grid, TPB>>>(W, x, scal, out4);
}

// round 11
// speedup vs baseline: 1.2335x; 1.2335x over previous
#include <cuda_runtime.h>
#include <cstdint>
#include <cstddef>

#define OUT_F 8192
#define IN_F  8192
#define NCOL  16
#define KS     16                 // K-splits across blockIdx.y
#define KSLICE (IN_F / KS)        // 512 k per block
#define K4SL   (KSLICE / 4)       // 128 packed k4 per block
#define PAD    36                 // smem words per k4 row (32 used; bank-conflict-free)
#define TPB    256
#define ROWS_PER_LANE 4
#define ROWS_PER_WARP 16          // 4 r-groups * 4 rows
#define ROWS_PER_BLK  128         // 8 warps * 16 rows
#define NGRP   (OUT_F / ROWS_PER_BLK)   // 64 row-groups
#define NITER  (K4SL / 8)         // 16: one k4 per kl-lane per iter

#define SXQ     4.8828125e-4f     // 2^-11 (x dequant scale)
#define SXQ_INV 2048.0f

// --- device scratch (no allocations allowed) ---
__device__ float4 psum4[KS * OUT_F * NCOL / 4];   // K-split partials (8 MiB)
__device__ int    g_cnt[NGRP];                    // arrival counters (self-resetting)

// Pack low bytes of 4 sign-extended int32 weights into one dp2a/dp4a word.
__device__ __forceinline__ uint32_t packw(uint4 v) {
    return (v.x & 0xFFu) | ((v.y & 0xFFu) << 8) | ((v.z & 0xFFu) << 16) | (v.w << 24);
}

// ------------------------------------------------------------------
// Single fused kernel: quantize x slice (int16) into padded SMEM,
// dp2a GEMM with coalesced prefetched W loads, warp-shuffle k-reduction,
// K-split partials, last-arriving-block tail reduction into out.
//   lane = r*8 + kl:  r in 0..3 -> rows 4r..4r+3,  kl in 0..7 -> k4.
//   x tile: s_x[k4*PAD + 2c]   = {xq[4k4],   xq[4k4+1]} (int16x2)
//           s_x[k4*PAD + 2c+1] = {xq[4k4+2], xq[4k4+3]}
//   LDS.128 at k4*PAD+4h -> banks 4(kl+h) mod 32: conflict-free.
//   dp2a_lo pairs (xq[k0],xq[k1]) with w bytes 0,1; dp2a_hi with bytes 2,3.
// ------------------------------------------------------------------
__global__ __launch_bounds__(TPB, 2)
void gemm_kernel(const int* __restrict__ W, const float* __restrict__ x,
                 const float* __restrict__ scal, float4* __restrict__ out4) {
    __shared__ uint32_t s_x[K4SL * PAD];   // 18 KB
    __shared__ int s_last;

    const int tid   = threadIdx.x;
    const int ky    = blockIdx.y;
    const int bx    = blockIdx.x;
    const int kbase = ky * KSLICE;

    // ---- stage + quantize x slice: x[k][c] row-major, k in [kbase, kbase+KSLICE) ----
    for (int slot = tid; slot < K4SL * NCOL; slot += TPB) {
        const int k4 = slot >> 4;
        const int c  = slot & 15;
        int q[4];
#pragma unroll
        for (int i = 0; i < 4; i++) {
            float v = x[(kbase + 4 * k4 + i) * NCOL + c];
            int t = __float2int_rn(v * SXQ_INV);
            q[i] = max(-32767, min(32767, t));
        }
        s_x[k4 * PAD + 2 * c]     = (uint32_t)(q[0] & 0xFFFF) | ((uint32_t)q[1] << 16);
        s_x[k4 * PAD + 2 * c + 1] = (uint32_t)(q[2] & 0xFFFF) | ((uint32_t)q[3] << 16);
    }
    __syncthreads();

    // ---- main loop ----
    const int lane = tid & 31;
    const int wid  = tid >> 5;
    const int r    = lane >> 3;            // 0..3
    const int kl   = lane & 7;             // 0..7
    const int row0 = bx * ROWS_PER_BLK + wid * ROWS_PER_WARP + 4 * r;

    const int* wp = W + (size_t)row0 * IN_F + kbase;

    int acc[ROWS_PER_LANE][NCOL];
#pragma unroll
    for (int j = 0; j < ROWS_PER_LANE; j++)
#pragma unroll
        for (int c = 0; c < NCOL; c++) acc[j][c] = 0;

    // prefetch iter 0
    uint4 pf[ROWS_PER_LANE];
#pragma unroll
    for (int j = 0; j < ROWS_PER_LANE; j++)
        pf[j] = __ldcs((const uint4*)(wp + (size_t)j * IN_F + kl * 4));

    for (int it = 0; it < NITER; it++) {
        const int k4 = it * 8 + kl;            // this lane's packed-k index

        uint32_t w[ROWS_PER_LANE];
#pragma unroll
        for (int j = 0; j < ROWS_PER_LANE; j++)
            w[j] = packw(pf[j]);

        if (it + 1 < NITER) {
            const int koff = ((it + 1) * 8 + kl) * 4;
#pragma unroll
            for (int j = 0; j < ROWS_PER_LANE; j++)
                pf[j] = __ldcs((const uint4*)(wp + (size_t)j * IN_F + koff));
        }

#pragma unroll
        for (int h = 0; h < 8; h++) {          // 2 columns per step
            uint4 X = *(const uint4*)&s_x[k4 * PAD + 4 * h];
            const int c0 = 2 * h, c1 = 2 * h + 1;
#pragma unroll
            for (int j = 0; j < ROWS_PER_LANE; j++) {
                acc[j][c0] = __dp2a_lo((int)X.x, (int)w[j], acc[j][c0]);
                acc[j][c0] = __dp2a_hi((int)X.y, (int)w[j], acc[j][c0]);
                acc[j][c1] = __dp2a_lo((int)X.z, (int)w[j], acc[j][c1]);
                acc[j][c1] = __dp2a_hi((int)X.w, (int)w[j], acc[j][c1]);
            }
        }
    }

    // ---- scale (exact int -> float), reduce across the 8 kl-lanes ----
    const float s = scal[0] * SXQ;
    float res[ROWS_PER_LANE][NCOL];
#pragma unroll
    for (int j = 0; j < ROWS_PER_LANE; j++)
#pragma unroll
        for (int c = 0; c < NCOL; c++)
            res[j][c] = s * (float)acc[j][c];

#pragma unroll
    for (int mask = 4; mask >= 1; mask >>= 1) {
#pragma unroll
        for (int j = 0; j < ROWS_PER_LANE; j++)
#pragma unroll
            for (int c = 0; c < NCOL; c++)
                res[j][c] += __shfl_xor_sync(0xFFFFFFFFu, res[j][c], mask);
    }

    if (kl == 0) {
#pragma unroll
        for (int j = 0; j < ROWS_PER_LANE; j++) {
            const int row = row0 + j;
            float4* dst = &psum4[((size_t)ky * OUT_F + row) * (NCOL / 4)];
#pragma unroll
            for (int c4 = 0; c4 < NCOL / 4; c4++)
                dst[c4] = make_float4(res[j][4 * c4], res[j][4 * c4 + 1],
                                      res[j][4 * c4 + 2], res[j][4 * c4 + 3]);
        }
    }

    // ---- tail: last of the KS blocks in this row-group reduces to out ----
    __threadfence();                 // publish psum writes
    if (tid == 0) {
        int old = atomicAdd(&g_cnt[bx], 1);
        int last = (old == KS - 1);
        if (last) g_cnt[bx] = 0;     // self-reset for next graph replay
        s_last = last;
    }
    __syncthreads();
    if (!s_last) return;
    __threadfence();                 // acquire other blocks' psum writes

    const int nf4 = ROWS_PER_BLK * NCOL / 4;            // 512
    for (int i4 = tid; i4 < nf4; i4 += TPB) {
        const int base = bx * nf4 + i4;                  // float4 index in slice 0
        float4 a = psum4[base];
#pragma unroll
        for (int j = 1; j < KS; j++) {
            float4 b = psum4[(size_t)j * (OUT_F * NCOL / 4) + base];
            a.x += b.x; a.y += b.y; a.z += b.z; a.w += b.w;
        }
        out4[base] = a;
    }
}

extern "C" void kernel_launch(void* const* d_in, const int* in_sizes, int n_in,
                              void* d_out, int out_size) {
    // Bind inputs by size (element counts; byte counts also accepted)
    const float* x    = nullptr;
    const int*   W    = nullptr;   // int8 weights delivered as int32 by harness
    const float* scal = nullptr;
    for (int i = 0; i < n_in; i++) {
        long sz = in_sizes[i];
        if (sz == (long)IN_F * NCOL || sz == (long)IN_F * NCOL * 4)
            x = (const float*)d_in[i];
        else if (sz == (long)OUT_F * IN_F || sz == (long)OUT_F * IN_F * 4)
            W = (const int*)d_in[i];
        else if (sz == 1 || sz == 4)
            scal = (const float*)d_in[i];
    }
    if (!x)    x    = (const float*)d_in[0];
    if (!W)    W    = (const int*)d_in[1];
    if (!scal) scal = (const float*)d_in[2];
    float4* out4 = (float4*)d_out;

    dim3 grid(NGRP, KS);   // (64, 16)
    gemm_kernel<<<grid, TPB>>>(W, x, scal, out4);
}

// round 13
// speedup vs baseline: 1.6475x; 1.3357x over previous
// Resubmission of R12: prior round failed in the GB300 broker (container
// error), not in the kernel. No measurement existed, so no design change.
#include <cuda_runtime.h>
#include <cuda_fp16.h>
#include <cstdint>
#include <cstddef>

#define OUT_F 8192
#define IN_F  8192
#define NCOL  16
#define KS     16                 // K-splits across blockIdx.y
#define KBLK   (IN_F / KS)        // 512 k per block
#define ST     258                // smem words per col (256 + 2 pad): conflict-free
#define TPB    256
#define ROWS_PER_WARP 16
#define ROWS_PER_BLK  128         // 8 warps * 16 rows
#define NGRP   (OUT_F / ROWS_PER_BLK)   // 64 row-groups
#define NIT    (KBLK / 64)        // 8 chunks of 64 k

// --- device scratch (no allocations allowed) ---
__device__ float psum[KS * OUT_F * NCOL];   // K-split partials (8 MiB)
__device__ int   g_cnt[NGRP];               // arrival counters (self-resetting)

// Pack low bytes of 4 sign-extended int32 weights into one word.
__device__ __forceinline__ uint32_t packw(uint4 v) {
    return (v.x & 0xFFu) | ((v.y & 0xFFu) << 8) | ((v.z & 0xFFu) << 16) | (v.w << 24);
}

// int8 -> fp16 exact conversion (magic number). Input already XOR 0x80808080.
// Validated: R2/R3 (this path) matched R4 scalar dp4a bit-for-bit in rel_err.
__device__ __forceinline__ uint32_t cvt_lo(uint32_t wx) {
    uint32_t p = __byte_perm(wx, 0x64006400u, 0x7150);   // {1024+b0, 1024+b1}
    uint32_t r;
    asm("add.rn.f16x2 %0, %1, %2;" : "=r"(r) : "r"(p), "r"(0xE480E480u)); // -1152
    return r;
}
__device__ __forceinline__ uint32_t cvt_hi(uint32_t wx) {
    uint32_t p = __byte_perm(wx, 0x64006400u, 0x7352);   // {1024+b2, 1024+b3}
    uint32_t r;
    asm("add.rn.f16x2 %0, %1, %2;" : "=r"(r) : "r"(p), "r"(0xE480E480u));
    return r;
}

// m16n8k8 fp16 MMA, fp32 accum. A row-major {a0: rows 0-7, a1: rows 8-15}.
__device__ __forceinline__ void mma1688(float* c, uint32_t a0, uint32_t a1, uint32_t b0) {
    asm volatile(
        "mma.sync.aligned.m16n8k8.row.col.f32.f16.f16.f32 "
        "{%0,%1,%2,%3}, {%4,%5}, {%6}, {%0,%1,%2,%3};"
        : "+f"(c[0]), "+f"(c[1]), "+f"(c[2]), "+f"(c[3])
        : "r"(a0), "r"(a1), "r"(b0));
}

// ------------------------------------------------------------------
// Fused kernel: split x slice into fp16 hi/lo in SMEM, fp16 MMA GEMM
// with coalesced int32-W loads + magic conversion, K-split partials,
// last-arriving-block tail reduction into out.
//   SMEM x tile: cols 0..15 = hi, 16..31 = lo; word kw = k_local/2.
//   B-fragment LDS.64 at (8t+r0)*ST + kw: banks 2r0+8cq distinct per
//   half-warp phase (ST=258 ≡ 2 mod 32) -> conflict-free.
// ------------------------------------------------------------------
__global__ __launch_bounds__(TPB, 2)
void gemm_kernel(const int* __restrict__ W, const float* __restrict__ x,
                 const float* __restrict__ scal, float4* __restrict__ out4) {
    __shared__ uint32_t s_x[32 * ST];      // 33 KB
    __shared__ int s_last;

    const int tid   = threadIdx.x;
    const int ky    = blockIdx.y;
    const int bx    = blockIdx.x;
    const int kbase = ky * KBLK;

    // ---- stage x slice as fp16 hi/lo pairs (exact split; no scale folded) ----
    for (int slot = tid; slot < (KBLK / 2) * NCOL; slot += TPB) {
        const int k2 = slot >> 4;          // 0..255: pair of k
        const int c  = slot & 15;
        float v0 = x[(kbase + 2 * k2)     * NCOL + c];
        float v1 = x[(kbase + 2 * k2 + 1) * NCOL + c];
        __half h0 = __float2half_rn(v0);
        __half h1 = __float2half_rn(v1);
        __half l0 = __float2half_rn(v0 - __half2float(h0));
        __half l1 = __float2half_rn(v1 - __half2float(h1));
        s_x[c * ST + k2] = (uint32_t)__half_as_ushort(h0)
                         | ((uint32_t)__half_as_ushort(h1) << 16);
        s_x[(c + 16) * ST + k2] = (uint32_t)__half_as_ushort(l0)
                                | ((uint32_t)__half_as_ushort(l1) << 16);
    }
    __syncthreads();

    // ---- main loop: warp = 16 rows x 32 B-cols, chunks of 64 k ----
    const int lane = tid & 31;
    const int wid  = tid >> 5;
    const int r0   = lane >> 2;            // 0..7: A-row group / B-col in tile
    const int cq   = lane & 3;             // 0..3: k-group within tile
    const int row0 = bx * ROWS_PER_BLK + wid * ROWS_PER_WARP;

    const int* wp = W + (size_t)(row0 + r0) * IN_F + kbase;

    float acc[4][4];                       // [t: n8 tile][c-frag]
#pragma unroll
    for (int t = 0; t < 4; t++)
#pragma unroll
        for (int i = 0; i < 4; i++) acc[t][i] = 0.f;

    for (int it = 0; it < NIT; it++) {
        const int k0 = it * 64 + cq * 16;  // this lane's 16-k window

        uint4 wq[2][4];                    // [row r0 / r0+8][q: 4-k group]
#pragma unroll
        for (int rs = 0; rs < 2; rs++)
#pragma unroll
            for (int q = 0; q < 4; q++)
                wq[rs][q] = __ldcs((const uint4*)(wp + (size_t)rs * 8 * IN_F + k0 + 4 * q));

#pragma unroll
        for (int g = 0; g < 4; g++) {
            const int kw = it * 32 + 8 * cq + 2 * g;   // half2 word index

            uint2 bb[4];
#pragma unroll
            for (int t = 0; t < 4; t++)
                bb[t] = *(const uint2*)&s_x[(8 * t + r0) * ST + kw];

            uint32_t w0 = packw(wq[0][g]) ^ 0x80808080u;   // row r0,   k..k+3
            uint32_t w1 = packw(wq[1][g]) ^ 0x80808080u;   // row r0+8, k..k+3
            uint32_t l0 = cvt_lo(w0), h0 = cvt_hi(w0);
            uint32_t l1 = cvt_lo(w1), h1 = cvt_hi(w1);
#pragma unroll
            for (int t = 0; t < 4; t++) {
                mma1688(acc[t], l0, l1, bb[t].x);   // k, k+1
                mma1688(acc[t], h0, h1, bb[t].y);   // k+2, k+3
            }
        }
    }

    // ---- epilogue: combine hi (t) + lo (t+2), scale, K-split partials ----
    const float s = scal[0];
#pragma unroll
    for (int i = 0; i < 2; i++) {          // c-frag row: r0 + 8i
        const int row = row0 + r0 + 8 * i;
#pragma unroll
        for (int t = 0; t < 2; t++) {      // cols 8t + 2cq
            float2 v;
            v.x = s * (acc[t][2 * i]     + acc[t + 2][2 * i]);
            v.y = s * (acc[t][2 * i + 1] + acc[t + 2][2 * i + 1]);
            *(float2*)&psum[((size_t)ky * OUT_F + row) * NCOL + 8 * t + 2 * cq] = v;
        }
    }

    // ---- tail: last of the KS blocks in this row-group reduces to out ----
    __threadfence();                 // publish psum writes
    if (tid == 0) {
        int old = atomicAdd(&g_cnt[bx], 1);
        int last = (old == KS - 1);
        if (last) g_cnt[bx] = 0;     // self-reset for next graph replay
        s_last = last;
    }
    __syncthreads();
    if (!s_last) return;
    __threadfence();                 // acquire other blocks' psum writes

    const float4* psum4 = (const float4*)psum;
    const int nf4 = ROWS_PER_BLK * NCOL / 4;            // 512
    for (int i4 = tid; i4 < nf4; i4 += TPB) {
        const int base = bx * nf4 + i4;                  // float4 index in slice 0
        float4 a = psum4[base];
#pragma unroll
        for (int j = 1; j < KS; j++) {
            float4 b = psum4[(size_t)j * (OUT_F * NCOL / 4) + base];
            a.x += b.x; a.y += b.y; a.z += b.z; a.w += b.w;
        }
        out4[base] = a;
    }
}

extern "C" void kernel_launch(void* const* d_in, const int* in_sizes, int n_in,
                              void* d_out, int out_size) {
    // Bind inputs by size (element counts; byte counts also accepted)
    const float* x    = nullptr;
    const int*   W    = nullptr;   // int8 weights delivered as int32 by harness
    const float* scal = nullptr;
    for (int i = 0; i < n_in; i++) {
        long sz = in_sizes[i];
        if (sz == (long)IN_F * NCOL || sz == (long)IN_F * NCOL * 4)
            x = (const float*)d_in[i];
        else if (sz == (long)OUT_F * IN_F || sz == (long)OUT_F * IN_F * 4)
            W = (const int*)d_in[i];
        else if (sz == 1 || sz == 4)
            scal = (const float*)d_in[i];
    }
    if (!x)    x    = (const float*)d_in[0];
    if (!W)    W    = (const int*)d_in[1];
    if (!scal) scal = (const float*)d_in[2];
    float4* out4 = (float4*)d_out;

    dim3 grid(NGRP, KS);   // (64, 16)
    gemm_kernel<<<grid, TPB>>>(W, x, scal, out4);
}